// round 16
// baseline (speedup 1.0000x reference)
#include <cuda_runtime.h>
#include <cstdint>

#define BATCH   1024
#define WDIM    256
#define HDIM    256
#define DEPTH   8
#define HMAX    256     // absolute worst-case hull size
#define HP      12      // padded fast-path hull size
#define NGRAN   (HP/2)  // 6 granules of 16B per w

#define F_INF   __int_as_float(0x7F800000)
#define F_NINF  __int_as_float(0xFF800000)

// Static device scratch (allocation-free rule).
// Transposed padded hulls: granule-major so warp-lane-consecutive w gives
// perfectly coalesced LDG.128. Granule g of w holds lines 2g,2g+1 as
// (m0, m1, b0, b1).
__device__ float2 g_hull  [2][DEPTH][WDIM][HMAX];   // oversized tail (k >= HP)
__device__ float4 g_hullpT[2][DEPTH][NGRAN][WDIM];  // 16B granule per (g, w)
__device__ int    g_cnt   [2][DEPTH][WDIM];

// Monotone float <-> uint key (uint order == float order, incl. +-inf).
__device__ __forceinline__ unsigned fkey(float f) {
    unsigned u = __float_as_uint(f);
    return (u & 0x80000000u) ? ~u : (u | 0x80000000u);
}
__device__ __forceinline__ float funkey(unsigned k) {
    unsigned u = (k & 0x80000000u) ? (k & 0x7FFFFFFFu) : ~k;
    return __uint_as_float(u);
}

// Packed f32x2 helpers (FFMA2 in SASS).
__device__ __forceinline__ uint64_t pack_dup(float f) {
    uint64_t r;
    asm("mov.b64 %0, {%1, %1};" : "=l"(r) : "f"(f));
    return r;
}
__device__ __forceinline__ void ffma2(uint64_t& d, uint64_t a, uint64_t b, uint64_t c) {
    asm("fma.rn.f32x2 %0, %1, %2, %3;" : "=l"(d) : "l"(a), "l"(b), "l"(c));
}
__device__ __forceinline__ void unpack2(float& lo, float& hi, uint64_t v) {
    asm("mov.b64 {%0, %1}, %2;" : "=f"(lo), "=f"(hi) : "l"(v));
}

// Write line k (k < HP) of w's padded hull in the TRANSPOSED layout.
__device__ __forceinline__ void store_line_T(float4* hbT, int w, int k,
                                             float m, float b) {
    int g = k >> 1, o = k & 1;
    float* c = (float*)(hbT + g * WDIM + w);
    c[o]     = m;
    c[2 + o] = b;
}

// ───────────────────────── hull kernel ─────────────────────────
// One warp per envelope (branch, d, w); max warp count (latency-bound steps).
// Proven R13 scan; transposed output. UNCHANGED from R15.
__global__ void __launch_bounds__(256) hull_kernel(
    const float* __restrict__ M1, const float* __restrict__ B1,
    const float* __restrict__ M2, const float* __restrict__ B2) {
    const int gw     = (blockIdx.x * blockDim.x + threadIdx.x) >> 5;  // 0..4095
    const int lane   = threadIdx.x & 31;
    const int branch = gw >> 11;
    const int d      = (gw >> 8) & 7;
    const int w      = gw & 255;

    const float* Mp = (branch ? M2 : M1) + (size_t)((d << 8) + w) * HDIM;
    const float* Bp = (branch ? B2 : B1) + (size_t)((d << 8) + w) * HDIM;

    float m[8], b[8];
    {
        const float4* M4 = (const float4*)Mp;
        const float4* B4 = (const float4*)Bp;
        float4 a0 = M4[lane * 2], a1 = M4[lane * 2 + 1];
        float4 c0 = B4[lane * 2], c1 = B4[lane * 2 + 1];
        m[0]=a0.x; m[1]=a0.y; m[2]=a0.z; m[3]=a0.w;
        m[4]=a1.x; m[5]=a1.y; m[6]=a1.z; m[7]=a1.w;
        b[0]=c0.x; b[1]=c0.y; b[2]=c0.z; b[3]=c0.w;
        b[4]=c1.x; b[5]=c1.y; b[6]=c1.z; b[7]=c1.w;
    }

    // Start line: min slope (dominated equal-slope start self-corrects).
    float mc = m[0], bc = b[0];
#pragma unroll
    for (int k = 1; k < 8; k++)
        if (m[k] < mc || (m[k] == mc && b[k] > bc)) { mc = m[k]; bc = b[k]; }
    {
        unsigned mk  = __reduce_min_sync(0xFFFFFFFFu, fkey(mc));
        unsigned bal = __ballot_sync(0xFFFFFFFFu, fkey(mc) == mk);
        int src = __ffs(bal) - 1;
        mc = __shfl_sync(0xFFFFFFFFu, mc, src);
        bc = __shfl_sync(0xFFFFFFFFu, bc, src);
    }

    float2* hf  = &g_hull[branch][d][w][0];
    float4* hbT = &g_hullpT[branch][d][0][0];
    const unsigned KEY_INF = fkey(F_INF);

    int cnt = 0;
    for (int step = 0; step < HMAX; ++step) {
        if (lane == 0) {
            if (cnt < HP) store_line_T(hbT, w, cnt, mc, bc);
            else          hf[cnt] = make_float2(mc, bc);
        }
        cnt++;

        // Per-lane: smallest crossing x among overtaking lines.
        // dj==0 && nj<0 encodes x = -inf via fdividef (-/0 -> -inf).
        float bx = F_INF, bm = 0.f, bb = 0.f;
#pragma unroll
        for (int k = 0; k < 8; k++) {
            float dj = m[k] - mc;
            float nj = bc - b[k];
            bool valid = (dj > 0.f) || (dj == 0.f && nj < 0.f);
            float x = valid ? __fdividef(nj, dj) : F_INF;
            if (x < bx) { bx = x; bm = m[k]; bb = b[k]; }
        }
        unsigned wk = __reduce_min_sync(0xFFFFFFFFu, fkey(bx));
        if (wk >= KEY_INF) break;                     // envelope complete
        unsigned bal = __ballot_sync(0xFFFFFFFFu, fkey(bx) == wk);
        int src = __ffs(bal) - 1;
        mc = __shfl_sync(0xFFFFFFFFu, bm, src);
        bc = __shfl_sync(0xFFFFFFFFu, bb, src);
    }

    // Pad the compact hull with (0, -inf): neutral for max.
    for (int k = cnt + lane; k < HP; k += 32)
        store_line_T(hbT, w, k, 0.f, F_NINF);
    if (lane == 0) g_cnt[branch][d][w] = cnt;
}

// ───────────────────────── eval kernel ─────────────────────────
// WARP-AUTONOMOUS: one warp owns 2 outputs (same branch, batches 2j, 2j+1)
// and covers ALL 256 w's itself: lane l handles w = 32k + l, k = 0..7.
// The layer->layer q dependency closes inside the warp with one REDUX per
// batch: NO __syncthreads, NO shared memory, NO cross-warp coupling.
// 1024 warps in 512 CTAs x 64 threads (~3.5 CTAs/SM). Granule loads are
// perfectly coalesced LDG.128 from the transposed layout (L1-resident).
__global__ void __launch_bounds__(64) eval_kernel(
    const float* __restrict__ val, float* __restrict__ out) {
    const int gw     = blockIdx.x * 2 + (threadIdx.x >> 5);  // 0..1023
    const int lane   = threadIdx.x & 31;
    const int branch = gw >> 9;
    const int b0     = (gw & 511) * 2;       // batches b0, b0+1

    float qf[2];
    qf[0] = val[b0];
    qf[1] = val[b0 + 1];

    for (int d = 0; d < DEPTH; ++d) {
        uint64_t q0 = pack_dup(qf[0]);
        uint64_t q1 = pack_dup(qf[1]);

        const ulonglong2* hb = (const ulonglong2*)&g_hullpT[branch][d][0][0];
        const int*        cp = &g_cnt[branch][d][0];

        // Pre-load all 8 hull sizes (coalesced) and gate the tail ONCE.
        int cw[8], mx = 0;
#pragma unroll
        for (int k = 0; k < 8; k++) {
            cw[k] = __ldg(cp + k * 32 + lane);
            mx = max(mx, cw[k]);
        }
        const bool big = __reduce_max_sync(0xFFFFFFFFu, (unsigned)mx) > HP;

        float vmin0 = F_INF, vmin1 = F_INF;

        if (!big) {            // fast path: every hull fits in 12 padded lines
#pragma unroll
            for (int k = 0; k < 8; k++) {
                const int w = k * 32 + lane;
                ulonglong2 P[NGRAN];
#pragma unroll
                for (int g = 0; g < NGRAN; g++)
                    P[g] = __ldg(hb + g * WDIM + w);

                float va0 = F_NINF, vb0 = F_NINF;
                float va1 = F_NINF, vb1 = F_NINF;
#pragma unroll
                for (int g = 0; g < NGRAN; g++) {
                    uint64_t s0, s1;
                    ffma2(s0, q0, P[g].x, P[g].y);
                    ffma2(s1, q1, P[g].x, P[g].y);
                    float l0, h0, l1, h1;
                    unpack2(l0, h0, s0);
                    unpack2(l1, h1, s1);
                    va0 = fmaxf(va0, l0); vb0 = fmaxf(vb0, h0);
                    va1 = fmaxf(va1, l1); vb1 = fmaxf(vb1, h1);
                }
                vmin0 = fminf(vmin0, fmaxf(va0, vb0));
                vmin1 = fminf(vmin1, fmaxf(va1, vb1));
            }
        } else {               // rare slow path: fold global tail into vmax
#pragma unroll
            for (int k = 0; k < 8; k++) {
                const int w = k * 32 + lane;
                ulonglong2 P[NGRAN];
#pragma unroll
                for (int g = 0; g < NGRAN; g++)
                    P[g] = __ldg(hb + g * WDIM + w);

                float va0 = F_NINF, vb0 = F_NINF;
                float va1 = F_NINF, vb1 = F_NINF;
#pragma unroll
                for (int g = 0; g < NGRAN; g++) {
                    uint64_t s0, s1;
                    ffma2(s0, q0, P[g].x, P[g].y);
                    ffma2(s1, q1, P[g].x, P[g].y);
                    float l0, h0, l1, h1;
                    unpack2(l0, h0, s0);
                    unpack2(l1, h1, s1);
                    va0 = fmaxf(va0, l0); vb0 = fmaxf(vb0, h0);
                    va1 = fmaxf(va1, l1); vb1 = fmaxf(vb1, h1);
                }
                float vmax0 = fmaxf(va0, vb0);
                float vmax1 = fmaxf(va1, vb1);
                if (cw[k] > HP) {                 // tail BEFORE the min
                    const float2* fp = &g_hull[branch][d][w][0];
                    for (int kk = HP; kk < cw[k]; kk++) {
                        float2 l2 = __ldg(fp + kk);
                        vmax0 = fmaxf(vmax0, fmaf(qf[0], l2.x, l2.y));
                        vmax1 = fmaxf(vmax1, fmaf(qf[1], l2.x, l2.y));
                    }
                }
                vmin0 = fminf(vmin0, vmax0);
                vmin1 = fminf(vmin1, vmax1);
            }
        }

        // q update: warp-wide min over all 256 w's (8 per lane), key domain.
        qf[0] = funkey(__reduce_min_sync(0xFFFFFFFFu, fkey(vmin0)));
        qf[1] = funkey(__reduce_min_sync(0xFFFFFFFFu, fkey(vmin1)));
    }

    if (lane == 0) {
        out[branch * BATCH + b0]     = qf[0];
        out[branch * BATCH + b0 + 1] = qf[1];
    }
}

extern "C" void kernel_launch(void* const* d_in, const int* in_sizes, int n_in,
                              void* d_out, int out_size) {
    const float* val = (const float*)d_in[0];
    const float* M1  = (const float*)d_in[1];
    const float* B1  = (const float*)d_in[2];
    const float* M2  = (const float*)d_in[3];
    const float* B2  = (const float*)d_in[4];
    float* out = (float*)d_out;

    hull_kernel<<<(2 * DEPTH * WDIM) / 8, 256>>>(M1, B1, M2, B2);
    eval_kernel<<<512, 64>>>(val, out);
}

// round 17
// speedup vs baseline: 2.4451x; 2.4451x over previous
#include <cuda_runtime.h>
#include <cstdint>

#define BATCH   1024
#define WDIM    256
#define HDIM    256
#define DEPTH   8
#define HMAX    256     // absolute worst-case hull size
#define HP      12      // padded fast-path hull size
#define NGRAN   (HP/2)  // 6 granules of 16B per w

#define F_INF   __int_as_float(0x7F800000)
#define F_NINF  __int_as_float(0xFF800000)

// Static device scratch (allocation-free rule).
// Transposed padded hulls: granule-major so warp-lane-consecutive w gives
// perfectly coalesced LDG.128. Granule g of w holds lines 2g,2g+1 as
// (m0, m1, b0, b1).
__device__ float2 g_hull  [2][DEPTH][WDIM][HMAX];   // oversized tail (k >= HP)
__device__ float4 g_hullpT[2][DEPTH][NGRAN][WDIM];  // 16B granule per (g, w)
__device__ int    g_cnt   [2][DEPTH][WDIM];

// Monotone float <-> uint key (uint order == float order, incl. +-inf).
__device__ __forceinline__ unsigned fkey(float f) {
    unsigned u = __float_as_uint(f);
    return (u & 0x80000000u) ? ~u : (u | 0x80000000u);
}
__device__ __forceinline__ float funkey(unsigned k) {
    unsigned u = (k & 0x80000000u) ? (k & 0x7FFFFFFFu) : ~k;
    return __uint_as_float(u);
}

// Packed f32x2 helpers (FFMA2 in SASS).
__device__ __forceinline__ uint64_t pack_dup(float f) {
    uint64_t r;
    asm("mov.b64 %0, {%1, %1};" : "=l"(r) : "f"(f));
    return r;
}
__device__ __forceinline__ void ffma2(uint64_t& d, uint64_t a, uint64_t b, uint64_t c) {
    asm("fma.rn.f32x2 %0, %1, %2, %3;" : "=l"(d) : "l"(a), "l"(b), "l"(c));
}
__device__ __forceinline__ void unpack2(float& lo, float& hi, uint64_t v) {
    asm("mov.b64 {%0, %1}, %2;" : "=f"(lo), "=f"(hi) : "l"(v));
}

// Write line k (k < HP) of w's padded hull in the TRANSPOSED layout.
__device__ __forceinline__ void store_line_T(float4* hbT, int w, int k,
                                             float m, float b) {
    int g = k >> 1, o = k & 1;
    float* c = (float*)(hbT + g * WDIM + w);
    c[o]     = m;
    c[2 + o] = b;
}

// Fraction candidate for the gift-wrap argmin: x = n/d with d >= 0.
// d==0: n<0 -> -inf (equal-slope strictly-above), n>0 -> +inf (invalid).
struct Cand { float n, d, m, b; };

// Is candidate A's crossing strictly before B's? Cross-multiplied compare
// (no division); exact up to fp rounding of the two products, which only
// reorders near-identical crossings (harmless for the envelope).
__device__ __forceinline__ bool cand_lt(const Cand& A, const Cand& B) {
    float pa = A.n * B.d;
    float pb = B.n * A.d;
    return (pa < pb) || (pa == pb && A.n < B.n);
}
__device__ __forceinline__ Cand cand_min(const Cand& A, const Cand& B) {
    return cand_lt(A, B) ? A : B;
}

// ───────────────────────── hull kernel ─────────────────────────
// One warp per envelope (branch, d, w). Per step: per-lane TREE argmin of 8
// crossing fractions via cross-mult (fma/alu pipes, log depth), then ONE
// fdividef on the lane winner for the REDUX key (MUFU per step: 16 -> 2).
// Warp argmin via lane-embedded key (no ballot).
__global__ void __launch_bounds__(256) hull_kernel(
    const float* __restrict__ M1, const float* __restrict__ B1,
    const float* __restrict__ M2, const float* __restrict__ B2) {
    const int gw     = (blockIdx.x * blockDim.x + threadIdx.x) >> 5;  // 0..4095
    const int lane   = threadIdx.x & 31;
    const int branch = gw >> 11;
    const int d      = (gw >> 8) & 7;
    const int w      = gw & 255;

    const float* Mp = (branch ? M2 : M1) + (size_t)((d << 8) + w) * HDIM;
    const float* Bp = (branch ? B2 : B1) + (size_t)((d << 8) + w) * HDIM;

    float m[8], b[8];
    {
        const float4* M4 = (const float4*)Mp;
        const float4* B4 = (const float4*)Bp;
        float4 a0 = M4[lane * 2], a1 = M4[lane * 2 + 1];
        float4 c0 = B4[lane * 2], c1 = B4[lane * 2 + 1];
        m[0]=a0.x; m[1]=a0.y; m[2]=a0.z; m[3]=a0.w;
        m[4]=a1.x; m[5]=a1.y; m[6]=a1.z; m[7]=a1.w;
        b[0]=c0.x; b[1]=c0.y; b[2]=c0.z; b[3]=c0.w;
        b[4]=c1.x; b[5]=c1.y; b[6]=c1.z; b[7]=c1.w;
    }

    // Start line: min slope; lane-embedded key (arbitrary 32-ulp tie pick is
    // fine — a dominated equal-slope start self-corrects via the -inf step).
    float mc = m[0], bc = b[0];
#pragma unroll
    for (int k = 1; k < 8; k++)
        if (m[k] < mc || (m[k] == mc && b[k] > bc)) { mc = m[k]; bc = b[k]; }
    {
        unsigned mk = __reduce_min_sync(0xFFFFFFFFu,
                                        (fkey(mc) & ~31u) | (unsigned)lane);
        int src = mk & 31;
        mc = __shfl_sync(0xFFFFFFFFu, mc, src);
        bc = __shfl_sync(0xFFFFFFFFu, bc, src);
    }

    float2* hf  = &g_hull[branch][d][w][0];
    float4* hbT = &g_hullpT[branch][d][0][0];

    int cnt = 0;
    for (int step = 0; step < HMAX; ++step) {
        if (lane == 0) {
            if (cnt < HP) store_line_T(hbT, w, cnt, mc, bc);
            else          hf[cnt] = make_float2(mc, bc);
        }
        cnt++;

        // Build 8 candidates; invalid -> (1, 0) = +inf.
        Cand c[8];
#pragma unroll
        for (int k = 0; k < 8; k++) {
            float dj = m[k] - mc;
            float nj = bc - b[k];
            bool valid = (dj > 0.f) || (dj == 0.f && nj < 0.f);
            c[k].n = valid ? nj : 1.f;
            c[k].d = valid ? dj : 0.f;
            c[k].m = m[k];
            c[k].b = b[k];
        }
        // Log-depth tree argmin (7 cross-mult compares, no MUFU).
        Cand c0 = cand_min(c[0], c[1]);
        Cand c1 = cand_min(c[2], c[3]);
        Cand c2 = cand_min(c[4], c[5]);
        Cand c3 = cand_min(c[6], c[7]);
        Cand c4 = cand_min(c0, c1);
        Cand c5 = cand_min(c2, c3);
        Cand cw_ = cand_min(c4, c5);

        // One divide to key the lane winner (d==0 -> +-inf, sign of n).
        float x = __fdividef(cw_.n, cw_.d);
        unsigned key = (fkey(x) & ~31u) | (unsigned)lane;

        unsigned wk = __reduce_min_sync(0xFFFFFFFFu, key);
        if (wk >= 0xFF800000u) break;     // winner is +inf -> envelope done
        int src = wk & 31;
        mc = __shfl_sync(0xFFFFFFFFu, cw_.m, src);
        bc = __shfl_sync(0xFFFFFFFFu, cw_.b, src);
    }

    // Pad the compact hull with (0, -inf): neutral for max.
    for (int k = cnt + lane; k < HP; k += 32)
        store_line_T(hbT, w, k, 0.f, F_NINF);
    if (lane == 0) g_cnt[branch][d][w] = cnt;
}

// ───────────────────────── eval kernel ─────────────────────────
// R15 proven shape, UNCHANGED: 256 CTAs (branch x group-of-8), 512 threads,
// 2 CTAs/SM; duo = t>>8 owns 4 batches, w = t&255; no staging (coalesced
// LDG.128 from transposed layout); key-domain reductions; parity s_red.
__global__ void __launch_bounds__(512, 2) eval_kernel(
    const float* __restrict__ val, float* __restrict__ out) {
    __shared__ uint4 s_red[2][16];   // [layer parity][duo*8 + wblk]

    const int t      = threadIdx.x;
    const int branch = blockIdx.x >> 7;
    const int grp8   = blockIdx.x & 127;
    const int warp   = t >> 5;
    const int lane   = t & 31;
    const int duo    = t >> 8;                   // 0..1 -> batches duo*4 .. +3
    const int w      = t & 255;                  // this thread's w, all layers

    float    qf[4];
    uint64_t q2[4];
#pragma unroll
    for (int i = 0; i < 4; i++) {
        qf[i] = val[grp8 * 8 + duo * 4 + i];
        q2[i] = pack_dup(qf[i]);
    }

    const ulonglong2* hb = (const ulonglong2*)&g_hullpT[branch][0][0][w];
    const int*        cp = &g_cnt[branch][0][w];

    for (int d = 0; d < DEPTH; ++d) {
        if (d > 0) {
            // Rebuild q: keys from the 8 wblk partials of my duo.
            uint4 r = s_red[(d - 1) & 1][duo * 8 + (lane & 7)];
#pragma unroll
            for (int off = 1; off <= 4; off <<= 1) {
                r.x = min(r.x, __shfl_xor_sync(0xFFFFFFFFu, r.x, off));
                r.y = min(r.y, __shfl_xor_sync(0xFFFFFFFFu, r.y, off));
                r.z = min(r.z, __shfl_xor_sync(0xFFFFFFFFu, r.z, off));
                r.w = min(r.w, __shfl_xor_sync(0xFFFFFFFFu, r.w, off));
            }
            qf[0] = funkey(r.x); qf[1] = funkey(r.y);
            qf[2] = funkey(r.z); qf[3] = funkey(r.w);
#pragma unroll
            for (int i = 0; i < 4; i++) q2[i] = pack_dup(qf[i]);
        }

        // Batch all 6 granules (MLP=6, coalesced, L1/L2-resident).
        ulonglong2 P[NGRAN];
#pragma unroll
        for (int g = 0; g < NGRAN; g++)
            P[g] = __ldg(hb + g * WDIM);

        // Dual accumulators per q: two FMNMX chains of 6.
        float va[4] = {F_NINF, F_NINF, F_NINF, F_NINF};
        float vb[4] = {F_NINF, F_NINF, F_NINF, F_NINF};
#pragma unroll
        for (int g = 0; g < NGRAN; g++) {
#pragma unroll
            for (int i = 0; i < 4; i++) {
                uint64_t s;
                ffma2(s, q2[i], P[g].x, P[g].y);   // lines 2g, 2g+1 at q[i]
                float lo, hi;
                unpack2(lo, hi, s);
                va[i] = fmaxf(va[i], lo);
                vb[i] = fmaxf(vb[i], hi);
            }
        }
        float vmax[4];
#pragma unroll
        for (int i = 0; i < 4; i++) vmax[i] = fmaxf(va[i], vb[i]);

        // Oversized hulls: warp-uniform gate; tail folds into vmax BEFORE min.
        int cw = __ldg(cp);
        if (__reduce_max_sync(0xFFFFFFFFu, (unsigned)cw) > HP) {
            if (cw > HP) {
                const float2* fp = &g_hull[branch][d][w][0];
                for (int k = HP; k < cw; k++) {
                    float2 l2 = __ldg(fp + k);
#pragma unroll
                    for (int i = 0; i < 4; i++)
                        vmax[i] = fmaxf(vmax[i], fmaf(qf[i], l2.x, l2.y));
                }
            }
        }

        // Warp-wide min over this warp's 32 w's, in key domain.
        uint4 kk;
        kk.x = __reduce_min_sync(0xFFFFFFFFu, fkey(vmax[0]));
        kk.y = __reduce_min_sync(0xFFFFFFFFu, fkey(vmax[1]));
        kk.z = __reduce_min_sync(0xFFFFFFFFu, fkey(vmax[2]));
        kk.w = __reduce_min_sync(0xFFFFFFFFu, fkey(vmax[3]));
        if (lane == 0) s_red[d & 1][duo * 8 + (warp & 7)] = kk;
        __syncthreads();   // publish partials; separates parity banks

        hb += NGRAN * WDIM;   // next layer
        cp += WDIM;
    }

    // Final combine: min over the 8 wblk partials of each duo, key domain.
    if (t < 8) {
        const int dd = t >> 2, ii = t & 3;
        unsigned acc = 0xFFFFFFFFu;
#pragma unroll
        for (int wb = 0; wb < 8; wb++) {
            uint4 r = s_red[(DEPTH - 1) & 1][dd * 8 + wb];
            unsigned v = (ii == 0) ? r.x : (ii == 1) ? r.y : (ii == 2) ? r.z : r.w;
            acc = min(acc, v);
        }
        out[branch * BATCH + grp8 * 8 + t] = funkey(acc);
    }
}

extern "C" void kernel_launch(void* const* d_in, const int* in_sizes, int n_in,
                              void* d_out, int out_size) {
    const float* val = (const float*)d_in[0];
    const float* M1  = (const float*)d_in[1];
    const float* B1  = (const float*)d_in[2];
    const float* M2  = (const float*)d_in[3];
    const float* B2  = (const float*)d_in[4];
    float* out = (float*)d_out;

    hull_kernel<<<(2 * DEPTH * WDIM) / 8, 256>>>(M1, B1, M2, B2);
    eval_kernel<<<256, 512>>>(val, out);
}